// round 17
// baseline (speedup 1.0000x reference)
#include <cuda_runtime.h>
#include <cstdint>

#define MN       1024
#define BATCH    2048
#define DIM      128
#define NITER_F  100.0f
#define ALPHA_F  0.3f
#define SIGMA_F  16.0f

// ---------------- scratch ----------------
__device__ unsigned long long g_part[8][BATCH];  // per-m-block argmin partials
__device__ float g_S[MN * DIM];
__device__ float g_cnt[MN];
__device__ unsigned g_sync[3];                   // grid barriers (self-reset)

__device__ __forceinline__ unsigned int f2ord(float f) {
    unsigned int u = __float_as_uint(f);
    return (u & 0x80000000u) ? ~u : (u | 0x80000000u);
}

__device__ __forceinline__ unsigned long long dupf(float f) {
    unsigned long long r;
    unsigned int u = __float_as_uint(f);
    asm("mov.b64 %0, {%1, %1};" : "=l"(r) : "r"(u));
    return r;
}

__device__ __forceinline__ void ffma2(unsigned long long& acc,
                                      unsigned long long a,
                                      unsigned long long b) {
    asm("fma.rn.f32x2 %0, %1, %2, %0;" : "+l"(acc) : "l"(a), "l"(b));
}

__device__ __forceinline__ float ldcg(const float* p) {
    float v;
    asm volatile("ld.global.cg.f32 %0, [%1];" : "=f"(v) : "l"(p));
    return v;
}
__device__ __forceinline__ float4 ldcg4(const float* p) {
    float4 v;
    asm volatile("ld.global.cg.v4.f32 {%0,%1,%2,%3}, [%4];"
                 : "=f"(v.x), "=f"(v.y), "=f"(v.z), "=f"(v.w) : "l"(p));
    return v;
}

// grid-wide barrier: all 128 co-resident blocks arrive, spin on .cv load
__device__ __forceinline__ void grid_bar(int idx) {
    __syncthreads();
    if (threadIdx.x == 0) {
        __threadfence();
        atomicAdd(&g_sync[idx], 1u);
        unsigned v;
        do {
            asm volatile("ld.global.cv.u32 %0, [%1];"
                         : "=r"(v) : "l"(&g_sync[idx]));
            if (v < 128u) __nanosleep(64);
        } while (v < 128u);
    }
    __syncthreads();
}

// ---------------- fused persistent kernel: bmu -> scatter -> tail ----------
// 128 blocks x 256 threads, 1 CTA/SM (147.5KB smem) -> all blocks co-resident.
__global__ __launch_bounds__(256, 1)
void k_som(const float* __restrict__ x, const float* __restrict__ w,
           const int* __restrict__ it, float* __restrict__ out) {
    extern __shared__ float smem[];
    float* Ws = smem;                                   // 128*128 f
    float* Xs = smem + 128 * 128;                       // 128*128 f
    unsigned long long* Red =
        (unsigned long long*)(smem + 2 * 128 * 128);    // [16][128]
    float* w2s = (float*)(Red + 16 * 128);              // [128]

    const int bid = blockIdx.x;          // 0..127
    const int tid = threadIdx.x;
    const int wrp = tid >> 5, lane = tid & 31;

    // ================= phase 1: BMU GEMM + argmin (R6 geometry) ============
    {
        const int m0 = (bid & 7) * 128;       // m-tile
        const int b0 = (bid >> 3) * 128;      // b-tile
        const int ty = (lane >> 2) | ((wrp & 1) << 3);      // 0..15
        const int tx = (lane & 3) | ((wrp >> 1) << 2);      // 0..15

        // zero scratch: 128 blocks x 1024 floats = all of g_S; g_cnt likewise
        *(float4*)&g_S[bid * 1024 + tid * 4] = make_float4(0.f, 0.f, 0.f, 0.f);
        if (tid < 2)
            *(float4*)&g_cnt[bid * 8 + tid * 4] = make_float4(0.f, 0.f, 0.f, 0.f);

        // stage both tiles one-shot (LDG.128 -> swizzled ST.128)
        #pragma unroll
        for (int i = 0; i < 16; i++) {
            int idx = tid + i * 256;          // 0..4095
            int row = idx >> 5;               // 0..127
            int g   = idx & 31;               // float4 group
            int sg  = (g ^ ((row >> 3) & 7)) << 2;
            float4 v = *(const float4*)&w[(m0 + row) * DIM + g * 4];
            *(float4*)&Ws[row * 128 + sg] = v;
            float4 u = *(const float4*)&x[(b0 + row) * DIM + g * 4];
            *(float4*)&Xs[row * 128 + sg] = u;
        }
        __syncthreads();

        // w2 from the staged tile (swizzle is a within-row permutation)
        if (tid < 128) {
            float s = 0.0f;
            #pragma unroll
            for (int g = 0; g < 32; g++) {
                float4 v = *(const float4*)&Ws[tid * 128 + g * 4];
                s += v.x * v.x + v.y * v.y + v.z * v.z + v.w * v.w;
            }
            w2s[tid] = s;
        }

        unsigned long long acc[8][8];
        #pragma unroll
        for (int mi = 0; mi < 8; mi++)
            #pragma unroll
            for (int bj = 0; bj < 8; bj++) acc[mi][bj] = 0ULL;

        const float* wbase = &Ws[(ty * 8) * 128];
        const float* xbase = &Xs[(tx * 8) * 128];
        const int sw = ty & 7;
        const int sx = tx & 7;

        #pragma unroll 1
        for (int kt = 0; kt < 32; kt++) {      // 4 k per step
            const int ow = (kt ^ sw) << 2;
            const int ox = (kt ^ sx) << 2;
            ulonglong2 xv[8];
            #pragma unroll
            for (int bj = 0; bj < 8; bj++)
                xv[bj] = *(const ulonglong2*)&xbase[bj * 128 + ox];
            #pragma unroll
            for (int mi = 0; mi < 8; mi++) {
                ulonglong2 wv = *(const ulonglong2*)&wbase[mi * 128 + ow];
                #pragma unroll
                for (int bj = 0; bj < 8; bj++) {
                    ffma2(acc[mi][bj], wv.x, xv[bj].x);
                    ffma2(acc[mi][bj], wv.y, xv[bj].y);
                }
            }
        }
        __syncthreads();   // w2s ready

        float w2r[8];
        #pragma unroll
        for (int mi = 0; mi < 8; mi++) w2r[mi] = w2s[ty * 8 + mi];

        #pragma unroll
        for (int bj = 0; bj < 8; bj++) {
            unsigned long long best = 0xFFFFFFFFFFFFFFFFULL;
            #pragma unroll
            for (int mi = 0; mi < 8; mi++) {
                float lo = __uint_as_float((unsigned int)(acc[mi][bj]));
                float hi = __uint_as_float((unsigned int)(acc[mi][bj] >> 32));
                float d2 = w2r[mi] - 2.0f * (lo + hi);
                unsigned long long key =
                    ((unsigned long long)f2ord(d2) << 32) |
                    (unsigned long long)(m0 + ty * 8 + mi);
                best = min(best, key);
            }
            Red[ty * 128 + tx * 8 + bj] = best;
        }
        __syncthreads();

        if (tid < 128) {
            unsigned long long best = Red[tid];
            #pragma unroll
            for (int t = 1; t < 16; t++) best = min(best, Red[t * 128 + tid]);
            g_part[bid & 7][b0 + tid] = best;   // plain store, no atomics
        }
    }

    grid_bar(0);

    // ================= phase 2: reduce partials + scatter ===================
    // 16 batch rows per block; one warp handles 2 rows.
    {
        #pragma unroll
        for (int r = 0; r < 2; r++) {
            int row = bid * 16 + wrp * 2 + r;
            unsigned long long v = 0xFFFFFFFFFFFFFFFFULL;
            if (lane < 8) {
                const unsigned long long* pp = &g_part[lane][row];
                asm volatile("ld.global.cg.u64 %0, [%1];" : "=l"(v) : "l"(pp));
            }
            #pragma unroll
            for (int o = 4; o >= 1; o >>= 1)
                v = min(v, __shfl_xor_sync(0xffffffffu, v, o));
            v = __shfl_sync(0xffffffffu, v, 0);
            int m = (int)(v & 0xFFFFFFFFULL);

            float4 vv = *(const float4*)&x[row * DIM + lane * 4];
            float* dst = &g_S[m * DIM + lane * 4];
            asm volatile("red.global.add.v4.f32 [%0], {%1, %2, %3, %4};"
                         :: "l"(dst), "f"(vv.x), "f"(vv.y), "f"(vv.z), "f"(vv.w)
                         : "memory");
            if (lane == 0) atomicAdd(&g_cnt[m], 1.0f);
        }
    }

    grid_bar(1);

    // ================= phase 3: separable gaussian contraction + update =====
    {
        float4* Ts = (float4*)smem;              // [32][9] float4, padded
        float* tc_s = smem + 32 * 9 * 4;         // [32]
        float* e_s  = tc_s + 32;                 // [32]

        const int cx = bid & 31;
        const int d0 = (bid >> 5) * 32;          // d-quarter base

        float lr_decay = 1.0f - (float)it[0] / NITER_F;
        float alpha_op = ALPHA_F * lr_decay;
        float sig = SIGMA_F * lr_decay;
        float inv_s2 = 1.0f / (sig * sig);

        if (tid < 32) e_s[tid] = expf(-(float)(tid * tid) * inv_s2);
        __syncthreads();

        // stage A: Ts[by][d] = sum_bx e(|cx-bx|) * S[by*32+bx][d]
        {
            const int by = tid >> 3;
            const int dq = tid & 7;
            const int d  = d0 + dq * 4;
            float4 a = make_float4(0.f, 0.f, 0.f, 0.f);
            #pragma unroll
            for (int bb = 0; bb < 4; bb++) {
                float4 sv[8];
                #pragma unroll
                for (int j = 0; j < 8; j++)
                    sv[j] = ldcg4(&g_S[(by * 32 + bb * 8 + j) * DIM + d]);
                #pragma unroll
                for (int j = 0; j < 8; j++) {
                    float e = e_s[abs(cx - (bb * 8 + j))];
                    a.x += e * sv[j].x; a.y += e * sv[j].y;
                    a.z += e * sv[j].z; a.w += e * sv[j].w;
                }
            }
            Ts[by * 9 + dq] = a;
        }
        if (tid < 32) {
            float c = 0.0f;
            #pragma unroll
            for (int bx = 0; bx < 32; bx++)
                c += e_s[abs(cx - bx)] * ldcg(&g_cnt[tid * 32 + bx]);
            tc_s[tid] = c;
        }
        __syncthreads();

        // stage B
        {
            const int cy = tid >> 3;
            const int dq = tid & 7;
            const int d  = d0 + dq * 4;
            float4 a = make_float4(0.f, 0.f, 0.f, 0.f);
            float s = 0.0f;
            #pragma unroll
            for (int by = 0; by < 32; by++) {
                float e = e_s[abs(cy - by)];
                float4 t = Ts[by * 9 + dq];
                a.x += e * t.x; a.y += e * t.y;
                a.z += e * t.z; a.w += e * t.w;
                s += e * tc_s[by];
            }
            const int c = (cy * 32 + cx) * DIM + d;
            float4 wv = *(const float4*)&w[c];
            float4 o;
            o.x = wv.x + alpha_op * (a.x - s * wv.x);
            o.y = wv.y + alpha_op * (a.y - s * wv.y);
            o.z = wv.z + alpha_op * (a.z - s * wv.z);
            o.w = wv.w + alpha_op * (a.w - s * wv.w);
            *(float4*)&out[c] = o;
        }
    }

    // cleanup: last block out resets the barrier counters for the next replay
    __syncthreads();
    if (tid == 0) {
        __threadfence();
        unsigned old = atomicAdd(&g_sync[2], 1u);
        if (old == 127u) {
            atomicExch(&g_sync[0], 0u);
            atomicExch(&g_sync[1], 0u);
            atomicExch(&g_sync[2], 0u);
        }
    }
}

// ---------------- launch ----------------
extern "C" void kernel_launch(void* const* d_in, const int* in_sizes, int n_in,
                              void* d_out, int out_size) {
    const float* x   = (const float*)d_in[0];   // [2048,128]
    const float* w   = (const float*)d_in[1];   // [1024,128]
    const int*   it  = (const int*)d_in[3];
    float* out = (float*)d_out;

    const int smem = 2 * 128 * 128 * 4 + 16 * 128 * 8 + 128 * 4;  // 147968 B
    cudaFuncSetAttribute(k_som, cudaFuncAttributeMaxDynamicSharedMemorySize,
                         smem);

    k_som<<<128, 256, smem>>>(x, w, it, out);
}